// round 16
// baseline (speedup 1.0000x reference)
#include <cuda_runtime.h>
#include <cuda_fp16.h>
#include <mma.h>
#include <math.h>
#include <stdint.h>
#include <stddef.h>

using namespace nvcuda;

#define Bb   8
#define Nn   4096
#define Dd   128
#define Pp   256
#define Kk   64
#define DFF  1024
#define BP   2048          // B*P patches
#define RT   131072        // BP*Kk point rows
#define EPSB 1e-5f

// ---------------- scratch (static device memory; no allocations) ----------------
__device__ int   d_fidx[BP];
__device__ int   d_gidx[RT];
__device__ float d_gxyz[RT * 3];
__device__ float d_pf[BP * Dd];
__device__ float d_ha[BP * DFF];
__device__ float d_hb[BP * DFF];
__device__ float d_coarse[BP * 48];
__device__ float d_base1[BP * DFF];
__device__ __half d_cw2h[DFF * DFF];             // BN-scaled fp16 cw2 [k][n] (2 MB)
__device__ __half d_h1h[(size_t)RT * DFF];       // fp16 h1 (256 MB)
__device__ float d_fine[RT * 3];
__device__ float d_partial[BP];

// ---------------- helpers ----------------
__device__ __forceinline__ unsigned int sptr(const void* p) {
    unsigned int a;
    asm("{ .reg .u64 t; cvta.to.shared.u64 t, %1; cvt.u32.u64 %0, t; }"
        : "=r"(a) : "l"(p));
    return a;
}
__device__ __forceinline__ void cpa16(unsigned int dst, const void* src) {
    asm volatile("cp.async.cg.shared.global [%0], [%1], 16;" :: "r"(dst), "l"(src));
}
__device__ __forceinline__ void cpcommit() {
    asm volatile("cp.async.commit_group;");
}

// ---------------- FPS: one block per batch, sequential 255 argmax steps ----------------
__global__ void fps_kernel(const float* __restrict__ xyz) {
    int b = blockIdx.x;
    const float* X = xyz + (size_t)b * Nn * 3;
    int t = threadIdx.x;  // 256 threads, 16 points each (strided)

    float px[16], py[16], pz[16], md[16];
#pragma unroll
    for (int i = 0; i < 16; i++) {
        int n = i * 256 + t;
        px[i] = X[n * 3 + 0]; py[i] = X[n * 3 + 1]; pz[i] = X[n * 3 + 2];
        md[i] = 1e10f;
    }
    __shared__ float scx, scy, scz;
    __shared__ float wv[8];
    __shared__ int   wi[8];
    if (t == 0) { d_fidx[b * Pp] = 0; scx = X[0]; scy = X[1]; scz = X[2]; }
    __syncthreads();

    for (int step = 1; step < Pp; step++) {
        float cx = scx, cy = scy, cz = scz;
        float bv = -1e30f; int bn = 0;
#pragma unroll
        for (int i = 0; i < 16; i++) {
            float dx = __fadd_rn(px[i], -cx);
            float dy = __fadd_rn(py[i], -cy);
            float dz = __fadd_rn(pz[i], -cz);
            float d  = __fadd_rn(__fadd_rn(__fmul_rn(dx, dx), __fmul_rn(dy, dy)),
                                 __fmul_rn(dz, dz));
            float m = fminf(md[i], d);
            md[i] = m;
            if (m > bv) { bv = m; bn = i * 256 + t; }
        }
#pragma unroll
        for (int off = 16; off; off >>= 1) {
            float ov = __shfl_down_sync(0xffffffffu, bv, off);
            int   on = __shfl_down_sync(0xffffffffu, bn, off);
            if (ov > bv || (ov == bv && on < bn)) { bv = ov; bn = on; }
        }
        if ((t & 31) == 0) { wv[t >> 5] = bv; wi[t >> 5] = bn; }
        __syncthreads();
        if (t == 0) {
            float fv = wv[0]; int fn = wi[0];
#pragma unroll
            for (int w = 1; w < 8; w++)
                if (wv[w] > fv || (wv[w] == fv && wi[w] < fn)) { fv = wv[w]; fn = wi[w]; }
            d_fidx[b * Pp + step] = fn;
            scx = X[fn * 3 + 0]; scy = X[fn * 3 + 1]; scz = X[fn * 3 + 2];
        }
        __syncthreads();
    }
}

// ---------------- top-K (64 nearest of 4096) per patch + grouped_xyz_norm ----------------
__global__ void topk_kernel(const float* __restrict__ xyz) {
    int pp = blockIdx.x;          // 0..2047
    int b  = pp >> 8;
    const float* X = xyz + (size_t)b * Nn * 3;
    int t = threadIdx.x;          // 256

    __shared__ float sd[16 * 256];
    __shared__ float wv[8];
    __shared__ int   wi[8];
    __shared__ int   sel;

    int cI = d_fidx[pp];
    float cx = X[cI * 3 + 0], cy = X[cI * 3 + 1], cz = X[cI * 3 + 2];

    float mv = 1e30f; int mn = 0x7fffffff;
#pragma unroll
    for (int i = 0; i < 16; i++) {
        int n = i * 256 + t;
        float dx = X[n * 3 + 0] - cx, dy = X[n * 3 + 1] - cy, dz = X[n * 3 + 2] - cz;
        float d = dx * dx + dy * dy + dz * dz;
        sd[i * 256 + t] = d;
        if (d < mv) { mv = d; mn = n; }
    }

    for (int k = 0; k < Kk; k++) {
        float v = mv; int n = mn;
#pragma unroll
        for (int off = 16; off; off >>= 1) {
            float ov = __shfl_down_sync(0xffffffffu, v, off);
            int   on = __shfl_down_sync(0xffffffffu, n, off);
            if (ov < v || (ov == v && on < n)) { v = ov; n = on; }
        }
        if ((t & 31) == 0) { wv[t >> 5] = v; wi[t >> 5] = n; }
        __syncthreads();
        if (t == 0) {
            float fv = wv[0]; int fn = wi[0];
#pragma unroll
            for (int w = 1; w < 8; w++)
                if (wv[w] < fv || (wv[w] == fv && wi[w] < fn)) { fv = wv[w]; fn = wi[w]; }
            sel = fn;
            d_gidx[pp * Kk + k] = fn;
            d_gxyz[(pp * Kk + k) * 3 + 0] = X[fn * 3 + 0] - cx;
            d_gxyz[(pp * Kk + k) * 3 + 1] = X[fn * 3 + 1] - cy;
            d_gxyz[(pp * Kk + k) * 3 + 2] = X[fn * 3 + 2] - cz;
        }
        __syncthreads();
        int s = sel;
        if ((s & 255) == t) {
            sd[(s >> 8) * 256 + t] = 1e30f;
            mv = 1e30f; mn = 0x7fffffff;
#pragma unroll
            for (int i = 0; i < 16; i++) {
                float d = sd[i * 256 + t];
                if (d < mv) { mv = d; mn = i * 256 + t; }
            }
        }
    }
}

// ---------------- patch feature: max over K neighbors ----------------
__global__ void pfeat_kernel(const float* __restrict__ feat) {
    int pp = blockIdx.x;          // 2048
    int b  = pp >> 8;
    int dch = threadIdx.x;        // 128
    const float* F = feat + (size_t)b * Nn * Dd;
    float mx = -1e30f;
#pragma unroll 4
    for (int k = 0; k < Kk; k++) {
        int n = d_gidx[pp * Kk + k];
        mx = fmaxf(mx, F[(size_t)n * Dd + dch]);
    }
    d_pf[pp * Dd + dch] = mx;
}

// ---------------- generic fp32 SGEMM 128x128x8 (small GEMMs only) ----------------
// mode 0: +bias ; mode 1: +bias, relu
__global__ __launch_bounds__(256) void sgemm_kernel(
    const float* __restrict__ A, const float* __restrict__ B, const float* __restrict__ bias,
    float* __restrict__ C, int M, int N, int K, int mode)
{
    __shared__ float As[8][128];
    __shared__ float Bs[8][128];
    int tid = threadIdx.x;
    int bx = blockIdx.x, by = blockIdx.y;
    int tx = tid & 15, ty = tid >> 4;
    int row0 = by * 128, col0 = bx * 128;
    int ar = tid >> 1, ac = (tid & 1) * 4;
    int br = tid >> 5, bc = (tid & 31) * 4;
    const float* Ap = A + (size_t)(row0 + ar) * K + ac;
    const float* Bp = B + (size_t)br * N + col0 + bc;

    float acc[8][8];
#pragma unroll
    for (int i = 0; i < 8; i++)
#pragma unroll
        for (int j = 0; j < 8; j++) acc[i][j] = 0.f;

    for (int kt = 0; kt < K; kt += 8) {
        float4 a4 = *(const float4*)(Ap + kt);
        float4 b4 = *(const float4*)(Bp + (size_t)kt * N);
        __syncthreads();
        As[ac + 0][ar] = a4.x; As[ac + 1][ar] = a4.y;
        As[ac + 2][ar] = a4.z; As[ac + 3][ar] = a4.w;
        *(float4*)(&Bs[br][bc]) = b4;
        __syncthreads();
#pragma unroll
        for (int k = 0; k < 8; k++) {
            float a[8], bfr[8];
#pragma unroll
            for (int i = 0; i < 8; i++) a[i] = As[k][ty * 8 + i];
#pragma unroll
            for (int j = 0; j < 8; j++) bfr[j] = Bs[k][tx * 8 + j];
#pragma unroll
            for (int i = 0; i < 8; i++)
#pragma unroll
                for (int j = 0; j < 8; j++) acc[i][j] = fmaf(a[i], bfr[j], acc[i][j]);
        }
    }

#pragma unroll
    for (int j = 0; j < 8; j++) {
        int c = col0 + tx * 8 + j;
        float tb = bias[c];
#pragma unroll
        for (int i = 0; i < 8; i++) {
            int r = row0 + ty * 8 + i;
            float x = acc[i][j] + tb;
            if (mode >= 1) x = fmaxf(x, 0.f);
            C[(size_t)r * N + c] = x;
        }
    }
}

// ---------------- MLP layer 3 (N=48): coarse = hb @ w3 + b3 ----------------
__global__ void mlp3_kernel(const float* __restrict__ w3, const float* __restrict__ b3) {
    int row = blockIdx.x;         // 2048
    __shared__ float a[1024];
    int t = threadIdx.x;          // 128
    for (int i = t; i < 1024; i += 128) a[i] = d_hb[(size_t)row * 1024 + i];
    __syncthreads();
    if (t < 48) {
        float s0 = 0.f, s1 = 0.f, s2 = 0.f, s3 = 0.f;
#pragma unroll 4
        for (int k = 0; k < 1024; k += 4) {
            s0 = fmaf(a[k + 0], w3[(k + 0) * 48 + t], s0);
            s1 = fmaf(a[k + 1], w3[(k + 1) * 48 + t], s1);
            s2 = fmaf(a[k + 2], w3[(k + 2) * 48 + t], s2);
            s3 = fmaf(a[k + 3], w3[(k + 3) * 48 + t], s3);
        }
        d_coarse[row * 48 + t] = ((s0 + s1) + (s2 + s3)) + b3[t];
    }
}

// ---------------- prescale cw2 by BN scale, convert to fp16 [k][n] ----------------
__global__ void prescale_kernel(const float* __restrict__ cw2,
                                const float* __restrict__ g2,
                                const float* __restrict__ v2) {
    int idx = blockIdx.x * 256 + threadIdx.x;   // 1M total
    int c = idx & 1023;
    float sc = g2[c] * rsqrtf(v2[c] + EPSB);
    d_cw2h[idx] = __float2half(cw2[idx] * sc);
}

// ---------------- conv layer 1 -> fp16 h1 (half2 stores): relu(bn(base1 + rank-5)) ----------------
__global__ void conv1h_kernel(const float* __restrict__ cw1, const float* __restrict__ g1,
                              const float* __restrict__ be1, const float* __restrict__ m1,
                              const float* __restrict__ v1) {
    int p = blockIdx.x;           // 2048 patches
    int t = threadIdx.x;          // 256 threads, 2 adjacent channels x 2 q-groups
    float u0[2][2], u1[2][2], u2[2][2], u3[2][2], u4[2][2], bb[2][2];
#pragma unroll
    for (int q = 0; q < 2; q++)
#pragma unroll
        for (int e = 0; e < 2; e++) {
            int j = q * 512 + t * 2 + e;
            float s = g1[j] * rsqrtf(v1[j] + EPSB);
            u0[q][e] = 0.05f * s * cw1[128 * 1024 + j];
            u1[q][e] = 0.05f * s * cw1[129 * 1024 + j];
            u2[q][e] = s * cw1[130 * 1024 + j];
            u3[q][e] = s * cw1[131 * 1024 + j];
            u4[q][e] = s * cw1[132 * 1024 + j];
            bb[q][e] = s * d_base1[p * 1024 + j] + (be1[j] - m1[j] * s);
        }
    for (int k = 0; k < 64; k++) {
        float sx = (k & 1) ? 1.f : -1.f;
        float sy = (k & 2) ? 1.f : -1.f;
        const float* cp = d_coarse + p * 48 + (k >> 2) * 3;
        float px = cp[0], py = cp[1], pz = cp[2];
        size_t rb = ((size_t)(p * 64 + k)) * 1024;
#pragma unroll
        for (int q = 0; q < 2; q++) {
            float e0 = bb[q][0] + sx * u0[q][0] + sy * u1[q][0]
                     + px * u2[q][0] + py * u3[q][0] + pz * u4[q][0];
            float e1 = bb[q][1] + sx * u0[q][1] + sy * u1[q][1]
                     + px * u2[q][1] + py * u3[q][1] + pz * u4[q][1];
            __half2 h = __floats2half2_rn(fmaxf(e0, 0.f), fmaxf(e1, 0.f));
            *(__half2*)(d_h1h + rb + q * 512 + t * 2) = h;
        }
    }
}

// ================= conv2 fp16 GEMM (fp16 acc): 128-row band, DUAL N-chunk, K-chunk 64 =================
// Block tile 128x256 per pass (4 passes), warp tile 64x32 per chunk, double buffer.
// One __syncthreads per K-iteration (trailing sync proven redundant by top-of-loop barrier).
#define KC    64
#define AB_LD 72                  // fp16 per A row (64 + 8 pad)
#define BB_LD 272                 // two 128-col chunks of (128+8) halves
#define A_T   (128 * AB_LD)       // 9216 halves
#define B_T   (KC * BB_LD)        // 17408 halves
#define C_LDH 136                 // half store ldm (mult of 8)
#define DYN_BYTES (2 * (A_T + B_T) * 2)   // 106496; epilogue Cs 128*136*2=34816 (reuse)

__global__ __launch_bounds__(256, 2) void conv2_gemm_kernel(
    const float* __restrict__ cb2, const float* __restrict__ g2,
    const float* __restrict__ be2, const float* __restrict__ m2,
    const float* __restrict__ v2,  const float* __restrict__ cw3,
    const float* __restrict__ cb3)
{
    extern __shared__ char dynS[];
    __half* As = (__half*)dynS;                      // [2][128][AB_LD]
    __half* Bs = (__half*)(dynS + 2 * A_T * 2);      // [2][KC][BB_LD]
    __half* Cs = (__half*)dynS;                      // reuse: [128][C_LDH]

    __shared__ float s_bias2[1024], s_w3x[1024], s_w3y[1024], s_w3z[1024];

    int tid = threadIdx.x;
    int wid = tid >> 5;
    int wm = wid >> 2;               // 0..1  (64-row group)
    int wn = wid & 3;                // 0..3  (32-col group within each chunk)
    int by = blockIdx.x;             // row band 0..1023
    int row0 = by * 128;

    for (int c = tid; c < 1024; c += 256) {
        float sc = g2[c] * rsqrtf(v2[c] + EPSB);
        s_bias2[c] = (cb2[c] - m2[c]) * sc + be2[c];
        s_w3x[c] = cw3[c * 3 + 0];
        s_w3y[c] = cw3[c * 3 + 1];
        s_w3z[c] = cw3[c * 3 + 2];
    }
    __syncthreads();

    // A: 128 rows x 64 halves = 1024 segs, 4/thread
    auto issueA = [&](int kt, int buf) {
#pragma unroll
        for (int s = 0; s < 4; s++) {
            int seg = tid + s * 256;
            int row = seg >> 3;
            int part = (seg & 7) * 8;
            unsigned int dst = sptr(As + buf * A_T + row * AB_LD + part);
            const __half* src = d_h1h + (size_t)(row0 + row) * 1024 + kt * KC + part;
            cpa16(dst, src);
        }
    };
    // B: 64 rows x 256 halves (2 chunks) = 2048 segs, 8/thread
    auto issueB = [&](int nc2, int kt, int buf) {
#pragma unroll
        for (int s = 0; s < 8; s++) {
            int seg = tid + s * 256;
            int r = seg >> 5;              // 0..63
            int s2 = seg & 31;             // 32 segs per row
            int chunk = s2 >> 4;
            int within = (s2 & 15) * 8;
            unsigned int dst = sptr(Bs + buf * B_T + r * BB_LD + chunk * 136 + within);
            const __half* src = d_cw2h + (size_t)(kt * KC + r) * 1024 + nc2 * 256 + s2 * 8;
            cpa16(dst, src);
        }
    };

    float fs0 = 0.f, fs1 = 0.f, fs2 = 0.f;      // per-thread half-row accumulators

    for (int nc2 = 0; nc2 < 4; nc2++) {
        wmma::fragment<wmma::accumulator, 16, 16, 16, __half> acc0[4][2], acc1[4][2];
#pragma unroll
        for (int mi = 0; mi < 4; mi++)
#pragma unroll
            for (int ni = 0; ni < 2; ni++) {
                wmma::fill_fragment(acc0[mi][ni], __float2half(0.f));
                wmma::fill_fragment(acc1[mi][ni], __float2half(0.f));
            }

        issueA(0, 0); issueB(nc2, 0, 0); cpcommit();

        for (int kt = 0; kt < 16; kt++) {
            int buf = kt & 1;
            asm volatile("cp.async.wait_group 0;");
            __syncthreads();
            if (kt < 15) { issueA(kt + 1, buf ^ 1); issueB(nc2, kt + 1, buf ^ 1); cpcommit(); }

            const __half* Ab = As + buf * A_T;
            const __half* Bb2 = Bs + buf * B_T;
#pragma unroll
            for (int kk = 0; kk < 4; kk++) {
                wmma::fragment<wmma::matrix_b, 16, 16, 16, __half, wmma::row_major> b00, b01, b10, b11;
                wmma::load_matrix_sync(b00, Bb2 + (kk * 16) * BB_LD + wn * 32, BB_LD);
                wmma::load_matrix_sync(b01, Bb2 + (kk * 16) * BB_LD + wn * 32 + 16, BB_LD);
                wmma::load_matrix_sync(b10, Bb2 + (kk * 16) * BB_LD + 136 + wn * 32, BB_LD);
                wmma::load_matrix_sync(b11, Bb2 + (kk * 16) * BB_LD + 136 + wn * 32 + 16, BB_LD);
#pragma unroll
                for (int mi = 0; mi < 4; mi++) {
                    wmma::fragment<wmma::matrix_a, 16, 16, 16, __half, wmma::row_major> af;
                    wmma::load_matrix_sync(af, Ab + (wm * 64 + mi * 16) * AB_LD + kk * 16, AB_LD);
                    wmma::mma_sync(acc0[mi][0], af, b00, acc0[mi][0]);
                    wmma::mma_sync(acc0[mi][1], af, b01, acc0[mi][1]);
                    wmma::mma_sync(acc1[mi][0], af, b10, acc1[mi][0]);
                    wmma::mma_sync(acc1[mi][1], af, b11, acc1[mi][1]);
                }
            }
            // no trailing sync: next iteration's top barrier orders buffer reuse
        }
        __syncthreads();   // all warps done reading stage buffers; Cs may overwrite

        // epilogue: two chunks, all 256 threads (thread: row tid>>1, col half (tid&1)*64)
#pragma unroll
        for (int chunk = 0; chunk < 2; chunk++) {
#pragma unroll
            for (int mi = 0; mi < 4; mi++)
#pragma unroll
                for (int ni = 0; ni < 2; ni++) {
                    if (chunk == 0)
                        wmma::store_matrix_sync(Cs + (wm * 64 + mi * 16) * C_LDH + wn * 32 + ni * 16,
                                                acc0[mi][ni], C_LDH, wmma::mem_row_major);
                    else
                        wmma::store_matrix_sync(Cs + (wm * 64 + mi * 16) * C_LDH + wn * 32 + ni * 16,
                                                acc1[mi][ni], C_LDH, wmma::mem_row_major);
                }
            __syncthreads();
            {
                int r = tid >> 1;
                int cs0 = (tid & 1) * 64;
                const __half* cr = Cs + r * C_LDH + cs0;
                int cb = nc2 * 256 + chunk * 128 + cs0;
#pragma unroll 4
                for (int c = 0; c < 64; c++) {
                    float x = fmaxf(__half2float(cr[c]) + s_bias2[cb + c], 0.f);
                    fs0 = fmaf(x, s_w3x[cb + c], fs0);
                    fs1 = fmaf(x, s_w3y[cb + c], fs1);
                    fs2 = fmaf(x, s_w3z[cb + c], fs2);
                }
            }
            __syncthreads();
        }
    }

    // combine col-half partials (lanes 2r, 2r+1 adjacent) and write fine
    float o0 = fs0 + __shfl_down_sync(0xffffffffu, fs0, 1);
    float o1 = fs1 + __shfl_down_sync(0xffffffffu, fs1, 1);
    float o2 = fs2 + __shfl_down_sync(0xffffffffu, fs2, 1);
    if ((tid & 1) == 0) {
        int row = row0 + (tid >> 1);
        int p = row >> 6, k = row & 63;
        const float* cp = d_coarse + p * 48 + (k >> 2) * 3;
        d_fine[row * 3 + 0] = o0 + cb3[0] + cp[0];
        d_fine[row * 3 + 1] = o1 + cb3[1] + cp[1];
        d_fine[row * 3 + 2] = o2 + cb3[2] + cp[2];
    }
}

// ---------------- Chamfer per patch ----------------
__global__ void chamfer_kernel() {
    int pt = blockIdx.x;          // 2048
    int t = threadIdx.x;          // 64
    __shared__ float F[64][3], G[64][3];
    const float* fr = d_fine + (size_t)pt * 64 * 3;
    const float* gr = d_gxyz + (size_t)pt * 64 * 3;
    for (int i = t; i < 192; i += 64) {
        ((float*)F)[i] = fr[i];
        ((float*)G)[i] = gr[i];
    }
    __syncthreads();
    float fx = F[t][0], fy = F[t][1], fz = F[t][2];
    float gx = G[t][0], gy = G[t][1], gz = G[t][2];
    float rmin = 1e30f, cmin = 1e30f;
#pragma unroll 4
    for (int s = 0; s < 64; s++) {
        float dx = fx - G[s][0], dy = fy - G[s][1], dz = fz - G[s][2];
        rmin = fminf(rmin, dx * dx + dy * dy + dz * dz);
        float ex = F[s][0] - gx, ey = F[s][1] - gy, ez = F[s][2] - gz;
        cmin = fminf(cmin, ex * ex + ey * ey + ez * ez);
    }
    float v = rmin + cmin;
#pragma unroll
    for (int off = 16; off; off >>= 1) v += __shfl_down_sync(0xffffffffu, v, off);
    __shared__ float ws[2];
    if ((t & 31) == 0) ws[t >> 5] = v;
    __syncthreads();
    if (t == 0) d_partial[pt] = ws[0] + ws[1];
}

// ---------------- deterministic final reduction ----------------
__global__ void final_kernel(float* __restrict__ out) {
    __shared__ float s[256];
    int t = threadIdx.x;
    float a = 0.f;
    for (int i = t; i < BP; i += 256) a += d_partial[i];
    s[t] = a;
    __syncthreads();
    for (int o = 128; o; o >>= 1) {
        if (t < o) s[t] += s[t + o];
        __syncthreads();
    }
    if (t == 0) out[0] = s[0] * (1.0f / 131072.0f);
}

// ---------------- launch ----------------
extern "C" void kernel_launch(void* const* d_in, const int* in_sizes, int n_in,
                              void* d_out, int out_size) {
    const float* xyz = (const float*)d_in[0];
    const float* feat = (const float*)d_in[1];
    const float* w1 = (const float*)d_in[2];  const float* b1 = (const float*)d_in[3];
    const float* w2 = (const float*)d_in[4];  const float* b2 = (const float*)d_in[5];
    const float* w3 = (const float*)d_in[6];  const float* b3 = (const float*)d_in[7];
    const float* cw1 = (const float*)d_in[8]; const float* cb1 = (const float*)d_in[9];
    const float* g1 = (const float*)d_in[10]; const float* be1 = (const float*)d_in[11];
    const float* m1 = (const float*)d_in[12]; const float* v1 = (const float*)d_in[13];
    const float* cw2 = (const float*)d_in[14]; const float* cb2 = (const float*)d_in[15];
    const float* g2 = (const float*)d_in[16]; const float* be2 = (const float*)d_in[17];
    const float* m2 = (const float*)d_in[18]; const float* v2 = (const float*)d_in[19];
    const float* cw3 = (const float*)d_in[20]; const float* cb3 = (const float*)d_in[21];

    float *p_pf, *p_ha, *p_hb, *p_base1;
    cudaGetSymbolAddress((void**)&p_pf, d_pf);
    cudaGetSymbolAddress((void**)&p_ha, d_ha);
    cudaGetSymbolAddress((void**)&p_hb, d_hb);
    cudaGetSymbolAddress((void**)&p_base1, d_base1);

    cudaFuncSetAttribute(conv2_gemm_kernel,
                         cudaFuncAttributeMaxDynamicSharedMemorySize, DYN_BYTES);

    fps_kernel<<<Bb, 256>>>(xyz);
    topk_kernel<<<BP, 256>>>(xyz);
    pfeat_kernel<<<BP, 128>>>(feat);

    // FoldingNet MLP on patch features
    sgemm_kernel<<<dim3(8, 16), 256>>>(p_pf, w1, b1, p_ha, BP, DFF, Dd, 1);
    sgemm_kernel<<<dim3(8, 16), 256>>>(p_ha, w2, b2, p_hb, BP, DFF, DFF, 1);
    mlp3_kernel<<<BP, 128>>>(w3, b3);

    // conv1 patch-level part (base1 = pf@cw1[:128]+cb1), weight prescale, fp16 h1
    sgemm_kernel<<<dim3(8, 16), 256>>>(p_pf, cw1, cb1, p_base1, BP, DFF, Dd, 0);
    prescale_kernel<<<DFF * DFF / 256, 256>>>(cw2, g2, v2);
    conv1h_kernel<<<BP, 256>>>(cw1, g1, be1, m1, v1);

    // conv2 fp16 GEMM (fp16 acc, dual N-chunk, K-chunk 64), fused BN+relu+conv3 -> d_fine
    conv2_gemm_kernel<<<RT / 128, 256, DYN_BYTES>>>(cb2, g2, be2, m2, v2, cw3, cb3);

    chamfer_kernel<<<BP, 64>>>();
    final_kernel<<<1, 256>>>((float*)d_out);
}

// round 17
// speedup vs baseline: 1.1146x; 1.1146x over previous
#include <cuda_runtime.h>
#include <cuda_fp16.h>
#include <mma.h>
#include <math.h>
#include <stdint.h>
#include <stddef.h>

using namespace nvcuda;

#define Bb   8
#define Nn   4096
#define Dd   128
#define Pp   256
#define Kk   64
#define DFF  1024
#define BP   2048          // B*P patches
#define RT   131072        // BP*Kk point rows
#define EPSB 1e-5f

// ---------------- scratch (static device memory; no allocations) ----------------
__device__ int   d_fidx[BP];
__device__ int   d_gidx[RT];
__device__ float d_gxyz[RT * 3];
__device__ float d_pf[BP * Dd];
__device__ float d_ha[BP * DFF];
__device__ float d_hb[BP * DFF];
__device__ float d_coarse[BP * 48];
__device__ float d_base1[BP * DFF];
__device__ __half d_cw2h[DFF * DFF];             // BN-scaled fp16 cw2 [k][n] (2 MB)
__device__ __half d_h1h[(size_t)RT * DFF];       // fp16 h1 (256 MB)
__device__ float d_fine[RT * 3];
__device__ float d_partial[BP];

// ---------------- helpers ----------------
__device__ __forceinline__ unsigned int sptr(const void* p) {
    unsigned int a;
    asm("{ .reg .u64 t; cvta.to.shared.u64 t, %1; cvt.u32.u64 %0, t; }"
        : "=r"(a) : "l"(p));
    return a;
}
__device__ __forceinline__ void cpa16(unsigned int dst, const void* src) {
    asm volatile("cp.async.cg.shared.global [%0], [%1], 16;" :: "r"(dst), "l"(src));
}
__device__ __forceinline__ void cpcommit() {
    asm volatile("cp.async.commit_group;");
}

// ---------------- FPS: one block per batch, sequential 255 argmax steps ----------------
__global__ void fps_kernel(const float* __restrict__ xyz) {
    int b = blockIdx.x;
    const float* X = xyz + (size_t)b * Nn * 3;
    int t = threadIdx.x;  // 256 threads, 16 points each (strided)

    float px[16], py[16], pz[16], md[16];
#pragma unroll
    for (int i = 0; i < 16; i++) {
        int n = i * 256 + t;
        px[i] = X[n * 3 + 0]; py[i] = X[n * 3 + 1]; pz[i] = X[n * 3 + 2];
        md[i] = 1e10f;
    }
    __shared__ float scx, scy, scz;
    __shared__ float wv[8];
    __shared__ int   wi[8];
    if (t == 0) { d_fidx[b * Pp] = 0; scx = X[0]; scy = X[1]; scz = X[2]; }
    __syncthreads();

    for (int step = 1; step < Pp; step++) {
        float cx = scx, cy = scy, cz = scz;
        float bv = -1e30f; int bn = 0;
#pragma unroll
        for (int i = 0; i < 16; i++) {
            float dx = __fadd_rn(px[i], -cx);
            float dy = __fadd_rn(py[i], -cy);
            float dz = __fadd_rn(pz[i], -cz);
            float d  = __fadd_rn(__fadd_rn(__fmul_rn(dx, dx), __fmul_rn(dy, dy)),
                                 __fmul_rn(dz, dz));
            float m = fminf(md[i], d);
            md[i] = m;
            if (m > bv) { bv = m; bn = i * 256 + t; }
        }
#pragma unroll
        for (int off = 16; off; off >>= 1) {
            float ov = __shfl_down_sync(0xffffffffu, bv, off);
            int   on = __shfl_down_sync(0xffffffffu, bn, off);
            if (ov > bv || (ov == bv && on < bn)) { bv = ov; bn = on; }
        }
        if ((t & 31) == 0) { wv[t >> 5] = bv; wi[t >> 5] = bn; }
        __syncthreads();
        if (t == 0) {
            float fv = wv[0]; int fn = wi[0];
#pragma unroll
            for (int w = 1; w < 8; w++)
                if (wv[w] > fv || (wv[w] == fv && wi[w] < fn)) { fv = wv[w]; fn = wi[w]; }
            d_fidx[b * Pp + step] = fn;
            scx = X[fn * 3 + 0]; scy = X[fn * 3 + 1]; scz = X[fn * 3 + 2];
        }
        __syncthreads();
    }
}

// ---------------- top-K (64 nearest of 4096) per patch + grouped_xyz_norm ----------------
__global__ void topk_kernel(const float* __restrict__ xyz) {
    int pp = blockIdx.x;          // 0..2047
    int b  = pp >> 8;
    const float* X = xyz + (size_t)b * Nn * 3;
    int t = threadIdx.x;          // 256

    __shared__ float sd[16 * 256];
    __shared__ float wv[8];
    __shared__ int   wi[8];
    __shared__ int   sel;

    int cI = d_fidx[pp];
    float cx = X[cI * 3 + 0], cy = X[cI * 3 + 1], cz = X[cI * 3 + 2];

    float mv = 1e30f; int mn = 0x7fffffff;
#pragma unroll
    for (int i = 0; i < 16; i++) {
        int n = i * 256 + t;
        float dx = X[n * 3 + 0] - cx, dy = X[n * 3 + 1] - cy, dz = X[n * 3 + 2] - cz;
        float d = dx * dx + dy * dy + dz * dz;
        sd[i * 256 + t] = d;
        if (d < mv) { mv = d; mn = n; }
    }

    for (int k = 0; k < Kk; k++) {
        float v = mv; int n = mn;
#pragma unroll
        for (int off = 16; off; off >>= 1) {
            float ov = __shfl_down_sync(0xffffffffu, v, off);
            int   on = __shfl_down_sync(0xffffffffu, n, off);
            if (ov < v || (ov == v && on < n)) { v = ov; n = on; }
        }
        if ((t & 31) == 0) { wv[t >> 5] = v; wi[t >> 5] = n; }
        __syncthreads();
        if (t == 0) {
            float fv = wv[0]; int fn = wi[0];
#pragma unroll
            for (int w = 1; w < 8; w++)
                if (wv[w] < fv || (wv[w] == fv && wi[w] < fn)) { fv = wv[w]; fn = wi[w]; }
            sel = fn;
            d_gidx[pp * Kk + k] = fn;
            d_gxyz[(pp * Kk + k) * 3 + 0] = X[fn * 3 + 0] - cx;
            d_gxyz[(pp * Kk + k) * 3 + 1] = X[fn * 3 + 1] - cy;
            d_gxyz[(pp * Kk + k) * 3 + 2] = X[fn * 3 + 2] - cz;
        }
        __syncthreads();
        int s = sel;
        if ((s & 255) == t) {
            sd[(s >> 8) * 256 + t] = 1e30f;
            mv = 1e30f; mn = 0x7fffffff;
#pragma unroll
            for (int i = 0; i < 16; i++) {
                float d = sd[i * 256 + t];
                if (d < mv) { mv = d; mn = i * 256 + t; }
            }
        }
    }
}

// ---------------- patch feature: max over K neighbors ----------------
__global__ void pfeat_kernel(const float* __restrict__ feat) {
    int pp = blockIdx.x;          // 2048
    int b  = pp >> 8;
    int dch = threadIdx.x;        // 128
    const float* F = feat + (size_t)b * Nn * Dd;
    float mx = -1e30f;
#pragma unroll 4
    for (int k = 0; k < Kk; k++) {
        int n = d_gidx[pp * Kk + k];
        mx = fmaxf(mx, F[(size_t)n * Dd + dch]);
    }
    d_pf[pp * Dd + dch] = mx;
}

// ---------------- generic fp32 SGEMM 128x128x8 (small GEMMs only) ----------------
// mode 0: +bias ; mode 1: +bias, relu
__global__ __launch_bounds__(256) void sgemm_kernel(
    const float* __restrict__ A, const float* __restrict__ B, const float* __restrict__ bias,
    float* __restrict__ C, int M, int N, int K, int mode)
{
    __shared__ float As[8][128];
    __shared__ float Bs[8][128];
    int tid = threadIdx.x;
    int bx = blockIdx.x, by = blockIdx.y;
    int tx = tid & 15, ty = tid >> 4;
    int row0 = by * 128, col0 = bx * 128;
    int ar = tid >> 1, ac = (tid & 1) * 4;
    int br = tid >> 5, bc = (tid & 31) * 4;
    const float* Ap = A + (size_t)(row0 + ar) * K + ac;
    const float* Bp = B + (size_t)br * N + col0 + bc;

    float acc[8][8];
#pragma unroll
    for (int i = 0; i < 8; i++)
#pragma unroll
        for (int j = 0; j < 8; j++) acc[i][j] = 0.f;

    for (int kt = 0; kt < K; kt += 8) {
        float4 a4 = *(const float4*)(Ap + kt);
        float4 b4 = *(const float4*)(Bp + (size_t)kt * N);
        __syncthreads();
        As[ac + 0][ar] = a4.x; As[ac + 1][ar] = a4.y;
        As[ac + 2][ar] = a4.z; As[ac + 3][ar] = a4.w;
        *(float4*)(&Bs[br][bc]) = b4;
        __syncthreads();
#pragma unroll
        for (int k = 0; k < 8; k++) {
            float a[8], bfr[8];
#pragma unroll
            for (int i = 0; i < 8; i++) a[i] = As[k][ty * 8 + i];
#pragma unroll
            for (int j = 0; j < 8; j++) bfr[j] = Bs[k][tx * 8 + j];
#pragma unroll
            for (int i = 0; i < 8; i++)
#pragma unroll
                for (int j = 0; j < 8; j++) acc[i][j] = fmaf(a[i], bfr[j], acc[i][j]);
        }
    }

#pragma unroll
    for (int j = 0; j < 8; j++) {
        int c = col0 + tx * 8 + j;
        float tb = bias[c];
#pragma unroll
        for (int i = 0; i < 8; i++) {
            int r = row0 + ty * 8 + i;
            float x = acc[i][j] + tb;
            if (mode >= 1) x = fmaxf(x, 0.f);
            C[(size_t)r * N + c] = x;
        }
    }
}

// ---------------- MLP layer 3 (N=48): coarse = hb @ w3 + b3 ----------------
__global__ void mlp3_kernel(const float* __restrict__ w3, const float* __restrict__ b3) {
    int row = blockIdx.x;         // 2048
    __shared__ float a[1024];
    int t = threadIdx.x;          // 128
    for (int i = t; i < 1024; i += 128) a[i] = d_hb[(size_t)row * 1024 + i];
    __syncthreads();
    if (t < 48) {
        float s0 = 0.f, s1 = 0.f, s2 = 0.f, s3 = 0.f;
#pragma unroll 4
        for (int k = 0; k < 1024; k += 4) {
            s0 = fmaf(a[k + 0], w3[(k + 0) * 48 + t], s0);
            s1 = fmaf(a[k + 1], w3[(k + 1) * 48 + t], s1);
            s2 = fmaf(a[k + 2], w3[(k + 2) * 48 + t], s2);
            s3 = fmaf(a[k + 3], w3[(k + 3) * 48 + t], s3);
        }
        d_coarse[row * 48 + t] = ((s0 + s1) + (s2 + s3)) + b3[t];
    }
}

// ---------------- prescale cw2 by BN scale, convert to fp16 [k][n] ----------------
__global__ void prescale_kernel(const float* __restrict__ cw2,
                                const float* __restrict__ g2,
                                const float* __restrict__ v2) {
    int idx = blockIdx.x * 256 + threadIdx.x;   // 1M total
    int c = idx & 1023;
    float sc = g2[c] * rsqrtf(v2[c] + EPSB);
    d_cw2h[idx] = __float2half(cw2[idx] * sc);
}

// ---------------- conv layer 1 -> fp16 h1 (half2 stores): relu(bn(base1 + rank-5)) ----------------
__global__ void conv1h_kernel(const float* __restrict__ cw1, const float* __restrict__ g1,
                              const float* __restrict__ be1, const float* __restrict__ m1,
                              const float* __restrict__ v1) {
    int p = blockIdx.x;           // 2048 patches
    int t = threadIdx.x;          // 256 threads, 2 adjacent channels x 2 q-groups
    float u0[2][2], u1[2][2], u2[2][2], u3[2][2], u4[2][2], bb[2][2];
#pragma unroll
    for (int q = 0; q < 2; q++)
#pragma unroll
        for (int e = 0; e < 2; e++) {
            int j = q * 512 + t * 2 + e;
            float s = g1[j] * rsqrtf(v1[j] + EPSB);
            u0[q][e] = 0.05f * s * cw1[128 * 1024 + j];
            u1[q][e] = 0.05f * s * cw1[129 * 1024 + j];
            u2[q][e] = s * cw1[130 * 1024 + j];
            u3[q][e] = s * cw1[131 * 1024 + j];
            u4[q][e] = s * cw1[132 * 1024 + j];
            bb[q][e] = s * d_base1[p * 1024 + j] + (be1[j] - m1[j] * s);
        }
    for (int k = 0; k < 64; k++) {
        float sx = (k & 1) ? 1.f : -1.f;
        float sy = (k & 2) ? 1.f : -1.f;
        const float* cp = d_coarse + p * 48 + (k >> 2) * 3;
        float px = cp[0], py = cp[1], pz = cp[2];
        size_t rb = ((size_t)(p * 64 + k)) * 1024;
#pragma unroll
        for (int q = 0; q < 2; q++) {
            float e0 = bb[q][0] + sx * u0[q][0] + sy * u1[q][0]
                     + px * u2[q][0] + py * u3[q][0] + pz * u4[q][0];
            float e1 = bb[q][1] + sx * u0[q][1] + sy * u1[q][1]
                     + px * u2[q][1] + py * u3[q][1] + pz * u4[q][1];
            __half2 h = __floats2half2_rn(fmaxf(e0, 0.f), fmaxf(e1, 0.f));
            *(__half2*)(d_h1h + rb + q * 512 + t * 2) = h;
        }
    }
}

// ================= conv2 fp16 GEMM (fp16 acc): 128-row band, DUAL N-chunk passes =================
// Block tile 128x256 per pass (4 passes), warp tile 64x32 per chunk, K-chunk 32, double buffer.
// ONE sync per K-iteration (trailing sync removed: top-of-loop barrier orders buffer reuse).
#define AB_LD 40                  // fp16 per A row (32 + 8 pad)
#define BB_LD 272                 // two 128-col chunks of (128+8) halves
#define A_T   (128 * AB_LD)       // 5120 halves
#define B_T   (32 * BB_LD)        // 8704 halves
#define C_LDH 136                 // half store ldm (mult of 8)
#define DYN_BYTES (2 * (A_T + B_T) * 2)   // 55296; epilogue Cs 128*136*2=34816 (reuse)

__global__ __launch_bounds__(256, 2) void conv2_gemm_kernel(
    const float* __restrict__ cb2, const float* __restrict__ g2,
    const float* __restrict__ be2, const float* __restrict__ m2,
    const float* __restrict__ v2,  const float* __restrict__ cw3,
    const float* __restrict__ cb3)
{
    extern __shared__ char dynS[];
    __half* As = (__half*)dynS;                      // [2][128][AB_LD]
    __half* Bs = (__half*)(dynS + 2 * A_T * 2);      // [2][32][BB_LD]
    __half* Cs = (__half*)dynS;                      // reuse: [128][C_LDH]

    __shared__ float s_bias2[1024], s_w3x[1024], s_w3y[1024], s_w3z[1024];

    int tid = threadIdx.x;
    int wid = tid >> 5;
    int wm = wid >> 2;               // 0..1  (64-row group)
    int wn = wid & 3;                // 0..3  (32-col group within each chunk)
    int by = blockIdx.x;             // row band 0..1023
    int row0 = by * 128;

    for (int c = tid; c < 1024; c += 256) {
        float sc = g2[c] * rsqrtf(v2[c] + EPSB);
        s_bias2[c] = (cb2[c] - m2[c]) * sc + be2[c];
        s_w3x[c] = cw3[c * 3 + 0];
        s_w3y[c] = cw3[c * 3 + 1];
        s_w3z[c] = cw3[c * 3 + 2];
    }
    __syncthreads();

    // A: 128 rows x 32 halves = 512 segs, 2/thread
    auto issueA = [&](int kt, int buf) {
#pragma unroll
        for (int s = 0; s < 2; s++) {
            int seg = tid + s * 256;
            int row = seg >> 2;
            int part = (seg & 3) * 8;
            unsigned int dst = sptr(As + buf * A_T + row * AB_LD + part);
            const __half* src = d_h1h + (size_t)(row0 + row) * 1024 + kt * 32 + part;
            cpa16(dst, src);
        }
    };
    // B: 32 rows x 256 halves (2 chunks) = 1024 segs, 4/thread
    auto issueB = [&](int nc2, int kt, int buf) {
#pragma unroll
        for (int s = 0; s < 4; s++) {
            int seg = tid + s * 256;
            int r = seg >> 5;              // 0..31
            int s2 = seg & 31;             // 32 segs per row
            int chunk = s2 >> 4;
            int within = (s2 & 15) * 8;
            unsigned int dst = sptr(Bs + buf * B_T + r * BB_LD + chunk * 136 + within);
            const __half* src = d_cw2h + (size_t)(kt * 32 + r) * 1024 + nc2 * 256 + s2 * 8;
            cpa16(dst, src);
        }
    };

    float fs0 = 0.f, fs1 = 0.f, fs2 = 0.f;      // per-thread half-row accumulators

    for (int nc2 = 0; nc2 < 4; nc2++) {
        wmma::fragment<wmma::accumulator, 16, 16, 16, __half> acc0[4][2], acc1[4][2];
#pragma unroll
        for (int mi = 0; mi < 4; mi++)
#pragma unroll
            for (int ni = 0; ni < 2; ni++) {
                wmma::fill_fragment(acc0[mi][ni], __float2half(0.f));
                wmma::fill_fragment(acc1[mi][ni], __float2half(0.f));
            }

        issueA(0, 0); issueB(nc2, 0, 0); cpcommit();

        for (int kt = 0; kt < 32; kt++) {
            int buf = kt & 1;
            asm volatile("cp.async.wait_group 0;");
            __syncthreads();
            if (kt < 31) { issueA(kt + 1, buf ^ 1); issueB(nc2, kt + 1, buf ^ 1); cpcommit(); }

            const __half* Ab = As + buf * A_T;
            const __half* Bb2 = Bs + buf * B_T;
#pragma unroll
            for (int kk = 0; kk < 2; kk++) {
                wmma::fragment<wmma::matrix_b, 16, 16, 16, __half, wmma::row_major> b00, b01, b10, b11;
                wmma::load_matrix_sync(b00, Bb2 + (kk * 16) * BB_LD + wn * 32, BB_LD);
                wmma::load_matrix_sync(b01, Bb2 + (kk * 16) * BB_LD + wn * 32 + 16, BB_LD);
                wmma::load_matrix_sync(b10, Bb2 + (kk * 16) * BB_LD + 136 + wn * 32, BB_LD);
                wmma::load_matrix_sync(b11, Bb2 + (kk * 16) * BB_LD + 136 + wn * 32 + 16, BB_LD);
#pragma unroll
                for (int mi = 0; mi < 4; mi++) {
                    wmma::fragment<wmma::matrix_a, 16, 16, 16, __half, wmma::row_major> af;
                    wmma::load_matrix_sync(af, Ab + (wm * 64 + mi * 16) * AB_LD + kk * 16, AB_LD);
                    wmma::mma_sync(acc0[mi][0], af, b00, acc0[mi][0]);
                    wmma::mma_sync(acc0[mi][1], af, b01, acc0[mi][1]);
                    wmma::mma_sync(acc1[mi][0], af, b10, acc1[mi][0]);
                    wmma::mma_sync(acc1[mi][1], af, b11, acc1[mi][1]);
                }
            }
            // no trailing sync: next iteration's top barrier orders buffer reuse
        }
        __syncthreads();   // all warps done reading stage buffers; Cs may overwrite

        // epilogue: two chunks, all 256 threads (thread: row tid>>1, col half (tid&1)*64)
#pragma unroll
        for (int chunk = 0; chunk < 2; chunk++) {
#pragma unroll
            for (int mi = 0; mi < 4; mi++)
#pragma unroll
                for (int ni = 0; ni < 2; ni++) {
                    if (chunk == 0)
                        wmma::store_matrix_sync(Cs + (wm * 64 + mi * 16) * C_LDH + wn * 32 + ni * 16,
                                                acc0[mi][ni], C_LDH, wmma::mem_row_major);
                    else
                        wmma::store_matrix_sync(Cs + (wm * 64 + mi * 16) * C_LDH + wn * 32 + ni * 16,
                                                acc1[mi][ni], C_LDH, wmma::mem_row_major);
                }
            __syncthreads();
            {
                int r = tid >> 1;
                int cs0 = (tid & 1) * 64;
                const __half* cr = Cs + r * C_LDH + cs0;
                int cb = nc2 * 256 + chunk * 128 + cs0;
#pragma unroll 4
                for (int c = 0; c < 64; c++) {
                    float x = fmaxf(__half2float(cr[c]) + s_bias2[cb + c], 0.f);
                    fs0 = fmaf(x, s_w3x[cb + c], fs0);
                    fs1 = fmaf(x, s_w3y[cb + c], fs1);
                    fs2 = fmaf(x, s_w3z[cb + c], fs2);
                }
            }
            __syncthreads();
        }
    }

    // combine col-half partials (lanes 2r, 2r+1 adjacent) and write fine
    float o0 = fs0 + __shfl_down_sync(0xffffffffu, fs0, 1);
    float o1 = fs1 + __shfl_down_sync(0xffffffffu, fs1, 1);
    float o2 = fs2 + __shfl_down_sync(0xffffffffu, fs2, 1);
    if ((tid & 1) == 0) {
        int row = row0 + (tid >> 1);
        int p = row >> 6, k = row & 63;
        const float* cp = d_coarse + p * 48 + (k >> 2) * 3;
        d_fine[row * 3 + 0] = o0 + cb3[0] + cp[0];
        d_fine[row * 3 + 1] = o1 + cb3[1] + cp[1];
        d_fine[row * 3 + 2] = o2 + cb3[2] + cp[2];
    }
}

// ---------------- Chamfer per patch ----------------
__global__ void chamfer_kernel() {
    int pt = blockIdx.x;          // 2048
    int t = threadIdx.x;          // 64
    __shared__ float F[64][3], G[64][3];
    const float* fr = d_fine + (size_t)pt * 64 * 3;
    const float* gr = d_gxyz + (size_t)pt * 64 * 3;
    for (int i = t; i < 192; i += 64) {
        ((float*)F)[i] = fr[i];
        ((float*)G)[i] = gr[i];
    }
    __syncthreads();
    float fx = F[t][0], fy = F[t][1], fz = F[t][2];
    float gx = G[t][0], gy = G[t][1], gz = G[t][2];
    float rmin = 1e30f, cmin = 1e30f;
#pragma unroll 4
    for (int s = 0; s < 64; s++) {
        float dx = fx - G[s][0], dy = fy - G[s][1], dz = fz - G[s][2];
        rmin = fminf(rmin, dx * dx + dy * dy + dz * dz);
        float ex = F[s][0] - gx, ey = F[s][1] - gy, ez = F[s][2] - gz;
        cmin = fminf(cmin, ex * ex + ey * ey + ez * ez);
    }
    float v = rmin + cmin;
#pragma unroll
    for (int off = 16; off; off >>= 1) v += __shfl_down_sync(0xffffffffu, v, off);
    __shared__ float ws[2];
    if ((t & 31) == 0) ws[t >> 5] = v;
    __syncthreads();
    if (t == 0) d_partial[pt] = ws[0] + ws[1];
}

// ---------------- deterministic final reduction ----------------
__global__ void final_kernel(float* __restrict__ out) {
    __shared__ float s[256];
    int t = threadIdx.x;
    float a = 0.f;
    for (int i = t; i < BP; i += 256) a += d_partial[i];
    s[t] = a;
    __syncthreads();
    for (int o = 128; o; o >>= 1) {
        if (t < o) s[t] += s[t + o];
        __syncthreads();
    }
    if (t == 0) out[0] = s[0] * (1.0f / 131072.0f);
}

// ---------------- launch ----------------
extern "C" void kernel_launch(void* const* d_in, const int* in_sizes, int n_in,
                              void* d_out, int out_size) {
    const float* xyz = (const float*)d_in[0];
    const float* feat = (const float*)d_in[1];
    const float* w1 = (const float*)d_in[2];  const float* b1 = (const float*)d_in[3];
    const float* w2 = (const float*)d_in[4];  const float* b2 = (const float*)d_in[5];
    const float* w3 = (const float*)d_in[6];  const float* b3 = (const float*)d_in[7];
    const float* cw1 = (const float*)d_in[8]; const float* cb1 = (const float*)d_in[9];
    const float* g1 = (const float*)d_in[10]; const float* be1 = (const float*)d_in[11];
    const float* m1 = (const float*)d_in[12]; const float* v1 = (const float*)d_in[13];
    const float* cw2 = (const float*)d_in[14]; const float* cb2 = (const float*)d_in[15];
    const float* g2 = (const float*)d_in[16]; const float* be2 = (const float*)d_in[17];
    const float* m2 = (const float*)d_in[18]; const float* v2 = (const float*)d_in[19];
    const float* cw3 = (const float*)d_in[20]; const float* cb3 = (const float*)d_in[21];

    float *p_pf, *p_ha, *p_hb, *p_base1;
    cudaGetSymbolAddress((void**)&p_pf, d_pf);
    cudaGetSymbolAddress((void**)&p_ha, d_ha);
    cudaGetSymbolAddress((void**)&p_hb, d_hb);
    cudaGetSymbolAddress((void**)&p_base1, d_base1);

    cudaFuncSetAttribute(conv2_gemm_kernel,
                         cudaFuncAttributeMaxDynamicSharedMemorySize, DYN_BYTES);

    fps_kernel<<<Bb, 256>>>(xyz);
    topk_kernel<<<BP, 256>>>(xyz);
    pfeat_kernel<<<BP, 128>>>(feat);

    // FoldingNet MLP on patch features
    sgemm_kernel<<<dim3(8, 16), 256>>>(p_pf, w1, b1, p_ha, BP, DFF, Dd, 1);
    sgemm_kernel<<<dim3(8, 16), 256>>>(p_ha, w2, b2, p_hb, BP, DFF, DFF, 1);
    mlp3_kernel<<<BP, 128>>>(w3, b3);

    // conv1 patch-level part (base1 = pf@cw1[:128]+cb1), weight prescale, fp16 h1
    sgemm_kernel<<<dim3(8, 16), 256>>>(p_pf, cw1, cb1, p_base1, BP, DFF, Dd, 0);
    prescale_kernel<<<DFF * DFF / 256, 256>>>(cw2, g2, v2);
    conv1h_kernel<<<BP, 256>>>(cw1, g1, be1, m1, v1);

    // conv2 fp16 GEMM (fp16 acc, dual N-chunk passes), fused BN+relu+conv3 -> d_fine
    conv2_gemm_kernel<<<RT / 128, 256, DYN_BYTES>>>(cb2, g2, be2, m2, v2, cw3, cb3);

    chamfer_kernel<<<BP, 64>>>();
    final_kernel<<<1, 256>>>((float*)d_out);
}